// round 6
// baseline (speedup 1.0000x reference)
#include <cuda_runtime.h>
#include <cuda_fp16.h>

#define G     512
#define GG    (G * G)
#define C     48
#define C2    (C / 2)
#define PPB   128                 // points per block in sampler
#define GRP   6                   // channel-octets per point
#define THREADS (PPB * GRP)       // 768
#define FSTR  75                  // s_feat2 row stride (half2 words), odd mod 32

// fp16 scratch (75.5 MB planes + 147 KB lines), layout [texel][channel]
__device__ __half g_planeH[3ULL * GG * C];
__device__ __half g_lineH[3ULL * G * C];

// ---------------------------------------------------------------------------
// Cache-hinted 128-bit loads
// ---------------------------------------------------------------------------
__device__ __forceinline__ uint4 ldg_ef(const __half* p) {   // planes: evict-first in L1
    uint4 v;
    asm("ld.global.nc.L1::evict_first.v4.u32 {%0,%1,%2,%3}, [%4];"
        : "=r"(v.x), "=r"(v.y), "=r"(v.z), "=r"(v.w) : "l"(p));
    return v;
}
__device__ __forceinline__ uint4 ldg_el(const __half* p) {   // lines: pin in L1
    uint4 v;
    asm("ld.global.nc.L1::evict_last.v4.u32 {%0,%1,%2,%3}, [%4];"
        : "=r"(v.x), "=r"(v.y), "=r"(v.z), "=r"(v.w) : "l"(p));
    return v;
}

// ---------------------------------------------------------------------------
// Transpose + fp32->fp16: in [C][GG] -> g_planeH [GG][C]. 128 texels/block.
// ---------------------------------------------------------------------------
#define TT 128
__global__ __launch_bounds__(256)
void tpose_plane_kernel(const float* __restrict__ p0,
                        const float* __restrict__ p1,
                        const float* __restrict__ p2) {
    __shared__ float tile[C][TT + 1];   // 48 x 129 fp32 = 24.8 KB
    const int pid = blockIdx.y;
    const float* in = (pid == 0) ? p0 : (pid == 1) ? p1 : p2;
    __half* out = g_planeH + (size_t)pid * GG * C;
    const int j0 = blockIdx.x * TT;

    #pragma unroll
    for (int i = threadIdx.x; i < C * (TT / 4); i += 256) {   // 1536 float4
        int c = i >> 5;
        int v = i & 31;
        float4 f = __ldg(reinterpret_cast<const float4*>(in + (size_t)c * GG + j0) + v);
        tile[c][4 * v + 0] = f.x;
        tile[c][4 * v + 1] = f.y;
        tile[c][4 * v + 2] = f.z;
        tile[c][4 * v + 3] = f.w;
    }
    __syncthreads();

    uint2* o2 = reinterpret_cast<uint2*>(out) + (size_t)j0 * 12;
    #pragma unroll
    for (int i = threadIdx.x; i < TT * 12; i += 256) {        // 1536 uint2
        int j  = i / 12;
        int c4 = i % 12;
        __half2 h0 = __float22half2_rn(make_float2(tile[4 * c4 + 0][j], tile[4 * c4 + 1][j]));
        __half2 h1 = __float22half2_rn(make_float2(tile[4 * c4 + 2][j], tile[4 * c4 + 3][j]));
        uint2 u;
        u.x = *reinterpret_cast<unsigned*>(&h0);
        u.y = *reinterpret_cast<unsigned*>(&h1);
        o2[i] = u;
    }
}

__global__ void tpose_line_kernel(const float* __restrict__ l0,
                                  const float* __restrict__ l1,
                                  const float* __restrict__ l2) {
    __shared__ float tile[64][50];
    const int pid = blockIdx.y;
    const float* in = (pid == 0) ? l0 : (pid == 1) ? l1 : l2;
    __half* out = g_lineH + (size_t)pid * G * C;
    const int j0 = blockIdx.x * 64;

    #pragma unroll
    for (int i = threadIdx.x; i < C * 64; i += 256) {
        int c = i >> 6;
        int j = i & 63;
        tile[j][c] = in[c * G + j0 + j];
    }
    __syncthreads();

    __half2* o2 = reinterpret_cast<__half2*>(out) + (size_t)j0 * C2;
    #pragma unroll
    for (int i = threadIdx.x; i < 64 * C2; i += 256) {
        int j  = i / C2;
        int c2 = i % C2;
        float2 v = *reinterpret_cast<const float2*>(&tile[j][2 * c2]);
        o2[i] = __float22half2_rn(v);
    }
}

// ---------------------------------------------------------------------------
// Sampler: thread = (channel-octet, point). Lines pinned in L1, planes stream.
// ---------------------------------------------------------------------------
__global__ __launch_bounds__(THREADS)
void sample_kernel(const float* __restrict__ xyz,
                   float* __restrict__ out, int N) {
    __shared__ int     s_t[3][PPB];
    __shared__ int     s_lz[3][PPB];
    __shared__ float   s_wx[3][PPB];
    __shared__ float   s_wy[3][PPB];
    __shared__ float   s_wz[3][PPB];
    __shared__ __half2 s_feat2[PPB * FSTR];   // [p][72 half2], 38.4 KB

    const int n0  = blockIdx.x * PPB;
    const int tid = threadIdx.x;

    // ---- Phase 0: per-(mode,point) indices & weights (384 threads) ----
    if (tid < 3 * PPB) {
        const int m = tid >> 7;      // 0..2
        const int p = tid & (PPB - 1);
        const int n = n0 + p;
        float x = 0.f, y = 0.f, z = 0.f;
        if (n < N) {
            x = xyz[3 * n + 0];
            y = xyz[3 * n + 1];
            z = xyz[3 * n + 2];
        }
        // MAT_MODE = [(0,1),(0,2),(1,2)], VEC_MODE = [2,1,0]
        const float gx = (m == 2) ? y : x;
        const float gy = (m == 0) ? y : z;
        const float gz = (m == 0) ? z : ((m == 1) ? y : x);

        float ix   = (gx + 1.0f) * 0.5f * (float)(G - 1);
        float iy   = (gy + 1.0f) * 0.5f * (float)(G - 1);
        float ix0f = fminf(fmaxf(floorf(ix), 0.0f), (float)(G - 1));
        float iy0f = fminf(fmaxf(floorf(iy), 0.0f), (float)(G - 1));
        int ix0 = (int)ix0f;
        int iy0 = (int)iy0f;
        s_t[m][p]  = iy0 * G + ix0;
        s_wx[m][p] = ix - ix0f;
        s_wy[m][p] = iy - iy0f;

        float iz   = (gz + 1.0f) * 0.5f * (float)(G - 1);
        float iz0f = fminf(fmaxf(floorf(iz), 0.0f), (float)(G - 1));
        int iz0 = (int)iz0f;
        s_lz[m][p] = iz0;
        s_wz[m][p] = iz - iz0f;
    }
    __syncthreads();

    // ---- Phase 1: gather fp16, interpolate fp32, stage as half2 ----
    {
        const int c8 = tid % GRP;    // 0..5
        const int p  = tid / GRP;    // 0..127
        #pragma unroll
        for (int m = 0; m < 3; m++) {
            const __half* P = g_planeH + (size_t)m * GG * C;
            const __half* L = g_lineH + (size_t)m * G * C;
            const int   t   = s_t[m][p];
            const int   ix0 = t & (G - 1);
            const int   iy0 = t >> 9;
            const int   dx  = (ix0 < G - 1) ? 1 : 0;
            const int   dy  = (iy0 < G - 1) ? G : 0;
            const float wx  = s_wx[m][p];
            const float wy  = s_wy[m][p];
            const int   lz  = s_lz[m][p];
            const int   dz  = (lz < G - 1) ? 1 : 0;
            const float wz  = s_wz[m][p];
            const int   co  = c8 * 8;   // channel offset

            uint4 q00 = ldg_ef(P + (size_t)t * C + co);
            uint4 q01 = ldg_ef(P + (size_t)(t + dx) * C + co);
            uint4 q10 = ldg_ef(P + (size_t)(t + dy) * C + co);
            uint4 q11 = ldg_ef(P + (size_t)(t + dy + dx) * C + co);
            uint4 ql0 = ldg_el(L + (size_t)lz * C + co);
            uint4 ql1 = ldg_el(L + (size_t)(lz + dz) * C + co);

            const unsigned* u00 = reinterpret_cast<const unsigned*>(&q00);
            const unsigned* u01 = reinterpret_cast<const unsigned*>(&q01);
            const unsigned* u10 = reinterpret_cast<const unsigned*>(&q10);
            const unsigned* u11 = reinterpret_cast<const unsigned*>(&q11);
            const unsigned* ul0 = reinterpret_cast<const unsigned*>(&ql0);
            const unsigned* ul1 = reinterpret_cast<const unsigned*>(&ql1);

            const int base = p * FSTR + m * 24 + c8 * 4;
            #pragma unroll
            for (int q = 0; q < 4; q++) {
                float2 a = __half22float2(*reinterpret_cast<const __half2*>(&u00[q]));
                float2 b = __half22float2(*reinterpret_cast<const __half2*>(&u01[q]));
                float2 c = __half22float2(*reinterpret_cast<const __half2*>(&u10[q]));
                float2 d = __half22float2(*reinterpret_cast<const __half2*>(&u11[q]));
                float2 e = __half22float2(*reinterpret_cast<const __half2*>(&ul0[q]));
                float2 f = __half22float2(*reinterpret_cast<const __half2*>(&ul1[q]));

                float2 top, bot, pl, ln, r;
                top.x = fmaf(wx, b.x - a.x, a.x);
                top.y = fmaf(wx, b.y - a.y, a.y);
                bot.x = fmaf(wx, d.x - c.x, c.x);
                bot.y = fmaf(wx, d.y - c.y, c.y);
                pl.x  = fmaf(wy, bot.x - top.x, top.x);
                pl.y  = fmaf(wy, bot.y - top.y, top.y);
                ln.x  = fmaf(wz, f.x - e.x, e.x);
                ln.y  = fmaf(wz, f.y - e.y, e.y);
                r.x = pl.x * ln.x;
                r.y = pl.y * ln.y;
                s_feat2[base + q] = __float22half2_rn(r);
            }
        }
    }
    __syncthreads();

    // ---- Phase 2: streaming coalesced fp32 stores ----
    {
        const int p  = tid & (PPB - 1);
        const int r0 = tid >> 7;       // 0..5
        const int n  = n0 + p;
        if (n < N) {
            #pragma unroll
            for (int i = 0; i < 12; i++) {
                const int cp = r0 + 6 * i;              // half2 index 0..71
                float2 f = __half22float2(s_feat2[p * FSTR + cp]);
                __stcs(out + (size_t)(2 * cp + 0) * N + n, f.x);
                __stcs(out + (size_t)(2 * cp + 1) * N + n, f.y);
            }
        }
    }
}

// ---------------------------------------------------------------------------
extern "C" void kernel_launch(void* const* d_in, const int* in_sizes, int n_in,
                              void* d_out, int out_size) {
    const float* xyz = (const float*)d_in[0];
    const float* p0  = (const float*)d_in[1];
    const float* p1  = (const float*)d_in[2];
    const float* p2  = (const float*)d_in[3];
    const float* l0  = (const float*)d_in[4];
    const float* l1  = (const float*)d_in[5];
    const float* l2  = (const float*)d_in[6];
    const int N = in_sizes[0] / 3;

    dim3 tpg(GG / TT, 3);
    tpose_plane_kernel<<<tpg, 256>>>(p0, p1, p2);
    dim3 tlg(G / 64, 3);
    tpose_line_kernel<<<tlg, 256>>>(l0, l1, l2);

    int nb = (N + PPB - 1) / PPB;
    sample_kernel<<<nb, THREADS>>>(xyz, (float*)d_out, N);
}

// round 11
// speedup vs baseline: 1.2221x; 1.2221x over previous
#include <cuda_runtime.h>
#include <cuda_fp16.h>

#define G     512
#define GG    (G * G)
#define C     48
#define C2    (C / 2)
#define PPB   64                  // points per block in sampler
#define GRP   6                   // channel-octets per point
#define THREADS 384               // PPB * GRP
#define TT    128                 // texels per transpose tile

// fp16 scratch (75.5 MB planes + 147 KB lines), layout [texel][channel]
__device__ __half g_planeH[3ULL * GG * C];
__device__ __half g_lineH[3ULL * G * C];

// ---------------------------------------------------------------------------
// Shared-memory overlays
// ---------------------------------------------------------------------------
struct TileSM {                       // transpose path: 24.8 KB
    float tile[C][TT + 1];
};
struct SampSM {                       // sampler path: 13.8 KB
    int   t[PPB];
    int   lz[PPB];
    float wx[PPB];
    float wy[PPB];
    float wz[PPB];
    float feat[C][PPB + 1];
};
#define SMEM_BYTES (sizeof(TileSM) > sizeof(SampSM) ? sizeof(TileSM) : sizeof(SampSM))

// ---------------------------------------------------------------------------
// Transpose body (384 threads): in [C][GG] fp32 -> out [GG][C] fp16
// ---------------------------------------------------------------------------
__device__ __forceinline__ void tpose_body(const float* __restrict__ in,
                                           __half* __restrict__ out,
                                           int blk, TileSM* sm) {
    const int j0  = blk * TT;
    const int tid = threadIdx.x;

    #pragma unroll
    for (int k = 0; k < 4; k++) {                 // 1536 float4 loads
        int i = tid + k * THREADS;
        int c = i >> 5;                           // /(TT/4)=32
        int v = i & 31;
        float4 f = __ldg(reinterpret_cast<const float4*>(in + (size_t)c * GG + j0) + v);
        sm->tile[c][4 * v + 0] = f.x;
        sm->tile[c][4 * v + 1] = f.y;
        sm->tile[c][4 * v + 2] = f.z;
        sm->tile[c][4 * v + 3] = f.w;
    }
    __syncthreads();

    uint2* o2 = reinterpret_cast<uint2*>(out) + (size_t)j0 * 12;
    #pragma unroll
    for (int k = 0; k < 4; k++) {                 // 1536 uint2 stores
        int i  = tid + k * THREADS;
        int j  = i / 12;
        int c4 = i % 12;
        __half2 h0 = __float22half2_rn(make_float2(sm->tile[4 * c4 + 0][j], sm->tile[4 * c4 + 1][j]));
        __half2 h1 = __float22half2_rn(make_float2(sm->tile[4 * c4 + 2][j], sm->tile[4 * c4 + 3][j]));
        uint2 u;
        u.x = *reinterpret_cast<unsigned*>(&h0);
        u.y = *reinterpret_cast<unsigned*>(&h1);
        o2[i] = u;
    }
}

// ---------------------------------------------------------------------------
// Sampler body for mode M (R4-proven structure)
// M=0: gx=x gy=y gz=z ; M=1: gx=x gy=z gz=y ; M=2: gx=y gy=z gz=x
// ---------------------------------------------------------------------------
template <int M>
__device__ __forceinline__ void sample_body(const float* __restrict__ xyz,
                                            float* __restrict__ out, int N,
                                            int blk, SampSM* sm) {
    const int n0  = blk * PPB;
    const int tid = threadIdx.x;

    // ---- Phase 0: per-point indices & weights ----
    if (tid < PPB) {
        int n = n0 + tid;
        float x = 0.f, y = 0.f, z = 0.f;
        if (n < N) {
            x = xyz[3 * n + 0];
            y = xyz[3 * n + 1];
            z = xyz[3 * n + 2];
        }
        const float gx = (M == 2) ? y : x;
        const float gy = (M == 0) ? y : z;
        const float gz = (M == 0) ? z : ((M == 1) ? y : x);

        float ix   = (gx + 1.0f) * 0.5f * (float)(G - 1);
        float iy   = (gy + 1.0f) * 0.5f * (float)(G - 1);
        float ix0f = fminf(fmaxf(floorf(ix), 0.0f), (float)(G - 1));
        float iy0f = fminf(fmaxf(floorf(iy), 0.0f), (float)(G - 1));
        int ix0 = (int)ix0f;
        int iy0 = (int)iy0f;
        sm->t[tid]  = iy0 * G + ix0;
        sm->wx[tid] = ix - ix0f;
        sm->wy[tid] = iy - iy0f;

        float iz   = (gz + 1.0f) * 0.5f * (float)(G - 1);
        float iz0f = fminf(fmaxf(floorf(iz), 0.0f), (float)(G - 1));
        int iz0 = (int)iz0f;
        sm->lz[tid] = iz0;
        sm->wz[tid] = iz - iz0f;
    }
    __syncthreads();

    // ---- Phase 1: gather fp16, interpolate fp32, stage to smem ----
    {
        const int c8 = tid % GRP;    // 0..5 (lanes contiguous in 96B texel)
        const int p  = tid / GRP;    // 0..63
        const __half* P = g_planeH + (size_t)M * GG * C;
        const __half* L = g_lineH + (size_t)M * G * C;

        const int   t   = sm->t[p];
        const int   ix0 = t & (G - 1);
        const int   iy0 = t >> 9;
        const int   dx  = (ix0 < G - 1) ? 1 : 0;
        const int   dy  = (iy0 < G - 1) ? G : 0;
        const float wx  = sm->wx[p];
        const float wy  = sm->wy[p];
        const int   lz  = sm->lz[p];
        const int   dz  = (lz < G - 1) ? 1 : 0;
        const float wz  = sm->wz[p];
        const int   co  = c8 * 8;

        uint4 q00 = __ldg(reinterpret_cast<const uint4*>(P + (size_t)t * C + co));
        uint4 q01 = __ldg(reinterpret_cast<const uint4*>(P + (size_t)(t + dx) * C + co));
        uint4 q10 = __ldg(reinterpret_cast<const uint4*>(P + (size_t)(t + dy) * C + co));
        uint4 q11 = __ldg(reinterpret_cast<const uint4*>(P + (size_t)(t + dy + dx) * C + co));
        uint4 ql0 = __ldg(reinterpret_cast<const uint4*>(L + (size_t)lz * C + co));
        uint4 ql1 = __ldg(reinterpret_cast<const uint4*>(L + (size_t)(lz + dz) * C + co));

        const unsigned* u00 = reinterpret_cast<const unsigned*>(&q00);
        const unsigned* u01 = reinterpret_cast<const unsigned*>(&q01);
        const unsigned* u10 = reinterpret_cast<const unsigned*>(&q10);
        const unsigned* u11 = reinterpret_cast<const unsigned*>(&q11);
        const unsigned* ul0 = reinterpret_cast<const unsigned*>(&ql0);
        const unsigned* ul1 = reinterpret_cast<const unsigned*>(&ql1);

        #pragma unroll
        for (int q = 0; q < 4; q++) {
            float2 a = __half22float2(*reinterpret_cast<const __half2*>(&u00[q]));
            float2 b = __half22float2(*reinterpret_cast<const __half2*>(&u01[q]));
            float2 c = __half22float2(*reinterpret_cast<const __half2*>(&u10[q]));
            float2 d = __half22float2(*reinterpret_cast<const __half2*>(&u11[q]));
            float2 e = __half22float2(*reinterpret_cast<const __half2*>(&ul0[q]));
            float2 f = __half22float2(*reinterpret_cast<const __half2*>(&ul1[q]));

            float2 top, bot, pl, ln;
            top.x = fmaf(wx, b.x - a.x, a.x);
            top.y = fmaf(wx, b.y - a.y, a.y);
            bot.x = fmaf(wx, d.x - c.x, c.x);
            bot.y = fmaf(wx, d.y - c.y, c.y);
            pl.x  = fmaf(wy, bot.x - top.x, top.x);
            pl.y  = fmaf(wy, bot.y - top.y, top.y);
            ln.x  = fmaf(wz, f.x - e.x, e.x);
            ln.y  = fmaf(wz, f.y - e.y, e.y);

            sm->feat[co + 2 * q + 0][p] = pl.x * ln.x;
            sm->feat[co + 2 * q + 1][p] = pl.y * ln.y;
        }
    }
    __syncthreads();

    // ---- Phase 2: coalesced fp32 stores ----
    {
        const int p  = tid & (PPB - 1);
        const int r0 = tid / PPB;        // 0..5
        const int n  = n0 + p;
        if (n < N) {
            #pragma unroll
            for (int i = 0; i < 8; i++) {
                const int r = r0 + i * 6;    // 0..47
                out[(size_t)r * N + n] = sm->feat[r][p];
            }
        }
    }
}

// ---------------------------------------------------------------------------
// Fused kernel: blocks [0,nS) sample mode M; blocks [nS,nS+nT) transpose
// plane (M+1). Sampler blocks lead so wave-1 isn't pure transpose.
// ---------------------------------------------------------------------------
template <int M>
__global__ __launch_bounds__(THREADS)
void fused_kernel(const float* __restrict__ xyz,
                  const float* __restrict__ plane_in,
                  float* __restrict__ out, int N, int nS) {
    __shared__ __align__(16) char smbuf[SMEM_BYTES];
    if ((int)blockIdx.x < nS) {
        sample_body<M>(xyz, out, N, blockIdx.x,
                       reinterpret_cast<SampSM*>(smbuf));
    } else {
        tpose_body(plane_in, g_planeH + (size_t)(M + 1) * GG * C,
                   blockIdx.x - nS, reinterpret_cast<TileSM*>(smbuf));
    }
}

// Standalone transpose of plane 0 (first kernel; nothing to overlap with).
__global__ __launch_bounds__(THREADS)
void tpose0_kernel(const float* __restrict__ in) {
    __shared__ __align__(16) char smbuf[SMEM_BYTES];
    tpose_body(in, g_planeH, blockIdx.x, reinterpret_cast<TileSM*>(smbuf));
}

__global__ void tpose_line_kernel(const float* __restrict__ l0,
                                  const float* __restrict__ l1,
                                  const float* __restrict__ l2) {
    __shared__ float tile[64][50];
    const int pid = blockIdx.y;
    const float* in = (pid == 0) ? l0 : (pid == 1) ? l1 : l2;
    __half* out = g_lineH + (size_t)pid * G * C;
    const int j0 = blockIdx.x * 64;

    #pragma unroll
    for (int i = threadIdx.x; i < C * 64; i += 256) {
        int c = i >> 6;
        int j = i & 63;
        tile[j][c] = in[c * G + j0 + j];
    }
    __syncthreads();

    __half2* o2 = reinterpret_cast<__half2*>(out) + (size_t)j0 * C2;
    #pragma unroll
    for (int i = threadIdx.x; i < 64 * C2; i += 256) {
        int j  = i / C2;
        int c2 = i % C2;
        float2 v = *reinterpret_cast<const float2*>(&tile[j][2 * c2]);
        o2[i] = __float22half2_rn(v);
    }
}

// ---------------------------------------------------------------------------
extern "C" void kernel_launch(void* const* d_in, const int* in_sizes, int n_in,
                              void* d_out, int out_size) {
    const float* xyz = (const float*)d_in[0];
    const float* p0  = (const float*)d_in[1];
    const float* p1  = (const float*)d_in[2];
    const float* p2  = (const float*)d_in[3];
    const float* l0  = (const float*)d_in[4];
    const float* l1  = (const float*)d_in[5];
    const float* l2  = (const float*)d_in[6];
    const int N = in_sizes[0] / 3;
    float* out = (float*)d_out;

    const int nT = GG / TT;                  // 2048 transpose blocks
    const int nS = (N + PPB - 1) / PPB;      // 8192 sampler blocks

    dim3 tlg(G / 64, 3);
    tpose_line_kernel<<<tlg, 256>>>(l0, l1, l2);
    tpose0_kernel<<<nT, THREADS>>>(p0);

    fused_kernel<0><<<nS + nT, THREADS>>>(xyz, p1, out + 0ULL * C * N, N, nS);
    fused_kernel<1><<<nS + nT, THREADS>>>(xyz, p2, out + 1ULL * C * N, N, nS);
    fused_kernel<2><<<nS, THREADS>>>(xyz, nullptr, out + 2ULL * C * N, N, nS);
}